// round 13
// baseline (speedup 1.0000x reference)
#include <cuda_runtime.h>
#include <math.h>
#include <stdint.h>

typedef unsigned long long u64;
typedef unsigned int u32;

// ---------------- problem constants ----------------
#define BN   2048
#define TSEQ 50
#define NSEQ 64
#define BB   32

// xp layout: [t][p][j*4 + gate]  (gate-interleaved for LDG.128 epilogues)

// ---------------- device scratch ----------------
__device__ float g_xp0[(size_t)TSEQ * BN * 512];
__device__ float g_xp1[(size_t)TSEQ * BN * 512];
__device__ float g_hbuf[2][2 * BN * 128];
__device__ float g_cst[2 * BN * 128];
__device__ float g_hsum[2 * BN * 128];
__device__ float g_sentpres[(size_t)BN * 256];
__device__ float g_txp0[(size_t)NSEQ * BB * 512];
__device__ float g_txp1[(size_t)NSEQ * BB * 512];
__device__ float g_thbuf[2][2 * BB * 128];
__device__ float g_tag_out[(size_t)BN * 256];
__device__ float g_q[(size_t)BN * 256];
__device__ float g_k[(size_t)BN * 256];
__device__ float g_sentFt[(size_t)BN * 15];
__device__ float g_roleFt[(size_t)BN * 15];
__device__ float g_agg[(size_t)BN * 256];
__device__ int g_tbar2[2 * 32];
__device__ int g_tdone2[2 * 32];
__device__ int g_sbar[32 * 32];
__device__ int g_sdone[32 * 32];

// ---------------- f32x2 helpers ----------------
__device__ __forceinline__ u64 pk2(float lo, float hi) {
    u64 r; asm("mov.b64 %0, {%1, %2};" : "=l"(r) : "f"(lo), "f"(hi)); return r;
}
__device__ __forceinline__ void up2(u64 v, float& lo, float& hi) {
    asm("mov.b64 {%0, %1}, %2;" : "=f"(lo), "=f"(hi) : "l"(v));
}
__device__ __forceinline__ void fma2(u64& d, u64 a, u64 b) {
    asm("fma.rn.f32x2 %0, %1, %2, %0;" : "+l"(d) : "l"(a), "l"(b));
}

// ---------------- tf32 helpers ----------------
__device__ __forceinline__ float tf32_rna(float x) {
    u32 u; asm("cvt.rna.tf32.f32 %0, %1;" : "=r"(u) : "f"(x));
    return __uint_as_float(u);
}
__device__ __forceinline__ void mma_tf32(float* d, const u32* a, const u32* b) {
    asm("mma.sync.aligned.m16n8k8.row.col.f32.tf32.tf32.f32 "
        "{%0,%1,%2,%3},{%4,%5,%6,%7},{%8,%9},{%0,%1,%2,%3};"
        : "+f"(d[0]), "+f"(d[1]), "+f"(d[2]), "+f"(d[3])
        : "r"(a[0]), "r"(a[1]), "r"(a[2]), "r"(a[3]), "r"(b[0]), "r"(b[1]));
}

// ---------------- fast math ----------------
__device__ __forceinline__ float sigf(float x) {
    x = fminf(fmaxf(x, -30.f), 30.f);
    return __fdividef(1.f, 1.f + __expf(-x));
}
__device__ __forceinline__ float tanhfast(float x) {
    x = fminf(fmaxf(x, -15.f), 15.f);
    return __fdividef(2.f, 1.f + __expf(-2.f * x)) - 1.f;
}

// ============================================================
// K1: sentence input projection with tensor cores (3xTF32).
// Epilogue writes gate-interleaved xp: [t][p][j*4+gate].
// Each block covers one gate (n0/128).
// ============================================================
#define K1P 12
__global__ void __launch_bounds__(256) gemm_inproj_tc(
    const float* __restrict__ A,
    const float* __restrict__ B0, const float* __restrict__ B1,
    const float* __restrict__ bias0, const float* __restrict__ bias1)
{
    __shared__ float sAh[2][128 * K1P], sAl[2][128 * K1P];
    __shared__ float sBh[2][128 * K1P], sBl[2][128 * K1P];

    int m0 = blockIdx.x * 128;
    int nb = blockIdx.y;
    int dir = nb >> 2;
    int gate = nb & 3;
    int n0 = gate * 128;
    const float* Bw = dir ? B1 : B0;
    const float* bias = dir ? bias1 : bias0;
    float* out = dir ? g_xp1 : g_xp0;

    int tid = threadIdx.x;
    int lane = tid & 31, warp = tid >> 5;
    int g = lane >> 2, tig = lane & 3;
    int wm = warp & 1, wn = warp >> 1;

    int srow = tid >> 1, shalf = tid & 1;
    const float* aP = A + (size_t)(m0 + srow) * 200 + shalf * 4;
    const float* bP = Bw + (size_t)(n0 + srow) * 200 + shalf * 4;

    float acc[4][4][4];
#pragma unroll
    for (int i = 0; i < 4; i++)
#pragma unroll
        for (int j = 0; j < 4; j++)
#pragma unroll
            for (int c = 0; c < 4; c++) acc[i][j][c] = 0.0f;

    float4 av = *(const float4*)aP;
    float4 bv = *(const float4*)bP;

    int soff = srow * K1P + shalf * 4;
#define K1_STAGE(buf, a4, b4) do {                                          \
        float4 _h, _l;                                                      \
        _h.x = tf32_rna(a4.x); _l.x = tf32_rna(a4.x - _h.x);                \
        _h.y = tf32_rna(a4.y); _l.y = tf32_rna(a4.y - _h.y);                \
        _h.z = tf32_rna(a4.z); _l.z = tf32_rna(a4.z - _h.z);                \
        _h.w = tf32_rna(a4.w); _l.w = tf32_rna(a4.w - _h.w);                \
        *(float4*)&sAh[buf][soff] = _h;                                     \
        *(float4*)&sAl[buf][soff] = _l;                                     \
        _h.x = tf32_rna(b4.x); _l.x = tf32_rna(b4.x - _h.x);                \
        _h.y = tf32_rna(b4.y); _l.y = tf32_rna(b4.y - _h.y);                \
        _h.z = tf32_rna(b4.z); _l.z = tf32_rna(b4.z - _h.z);                \
        _h.w = tf32_rna(b4.w); _l.w = tf32_rna(b4.w - _h.w);                \
        *(float4*)&sBh[buf][soff] = _h;                                     \
        *(float4*)&sBl[buf][soff] = _l;                                     \
    } while (0)

    K1_STAGE(0, av, bv);
    __syncthreads();

    for (int kt = 0; kt < 25; kt++) {
        int cur = kt & 1;
        if (kt < 24) {
            av = *(const float4*)(aP + (kt + 1) * 8);
            bv = *(const float4*)(bP + (kt + 1) * 8);
        }
        u32 bh[4][2], bl[4][2];
#pragma unroll
        for (int nt = 0; nt < 4; nt++) {
            int br = (wn * 32 + nt * 8 + g) * K1P;
            bh[nt][0] = __float_as_uint(sBh[cur][br + tig]);
            bh[nt][1] = __float_as_uint(sBh[cur][br + tig + 4]);
            bl[nt][0] = __float_as_uint(sBl[cur][br + tig]);
            bl[nt][1] = __float_as_uint(sBl[cur][br + tig + 4]);
        }
#pragma unroll
        for (int mt = 0; mt < 4; mt++) {
            int ar0 = (wm * 64 + mt * 16 + g) * K1P;
            int ar1 = ar0 + 8 * K1P;
            u32 ah[4], al[4];
            ah[0] = __float_as_uint(sAh[cur][ar0 + tig]);
            ah[1] = __float_as_uint(sAh[cur][ar1 + tig]);
            ah[2] = __float_as_uint(sAh[cur][ar0 + tig + 4]);
            ah[3] = __float_as_uint(sAh[cur][ar1 + tig + 4]);
            al[0] = __float_as_uint(sAl[cur][ar0 + tig]);
            al[1] = __float_as_uint(sAl[cur][ar1 + tig]);
            al[2] = __float_as_uint(sAl[cur][ar0 + tig + 4]);
            al[3] = __float_as_uint(sAl[cur][ar1 + tig + 4]);
#pragma unroll
            for (int nt = 0; nt < 4; nt++) {
                mma_tf32(acc[mt][nt], ah, bh[nt]);
                mma_tf32(acc[mt][nt], al, bh[nt]);
                mma_tf32(acc[mt][nt], ah, bl[nt]);
            }
        }
        __syncthreads();
        if (kt < 24) {
            K1_STAGE((kt + 1) & 1, av, bv);
            __syncthreads();
        }
    }

    // epilogue: gate-interleaved scatter [t][p][j*4+gate]
#pragma unroll
    for (int mt = 0; mt < 4; mt++) {
#pragma unroll
        for (int nt = 0; nt < 4; nt++) {
            int jcol = wn * 32 + nt * 8 + 2 * tig;
            float b0v = __ldg(bias + n0 + jcol), b1v = __ldg(bias + n0 + jcol + 1);
            int r0 = m0 + wm * 64 + mt * 16 + g;
            int p0 = r0 / 50, t0 = r0 - p0 * 50;
            size_t rb0 = ((size_t)t0 * BN + p0) * 512;
            out[rb0 + jcol * 4 + gate] = acc[mt][nt][0] + b0v;
            out[rb0 + (jcol + 1) * 4 + gate] = acc[mt][nt][1] + b1v;
            int r1 = r0 + 8;
            int p1 = r1 / 50, t1 = r1 - p1 * 50;
            size_t rb1 = ((size_t)t1 * BN + p1) * 512;
            out[rb1 + jcol * 4 + gate] = acc[mt][nt][2] + b0v;
            out[rb1 + (jcol + 1) * 4 + gate] = acc[mt][nt][3] + b1v;
        }
    }
}

// ============================================================
// Sentence LSTM: PERSISTENT tensor-core recurrence, 512 threads.
// xp prefetched at step start (LDG.128, gate-interleaved).
// ============================================================
#define S5_WST   132
#define S5_HST   36
#define S5_WSZ   (128 * S5_WST)
#define S5_HBUF  (2 * 128 * S5_HST)
#define S5_SMEM  ((2 * S5_WSZ + 2 * S5_HBUF) * 4)

__global__ void __launch_bounds__(512, 1) lstm_sent5(
    const float* __restrict__ W0, const float* __restrict__ W1)
{
    extern __shared__ __align__(16) float s5[];
    float* sWh = s5;
    float* sWl = s5 + S5_WSZ;
    float* sH  = s5 + 2 * S5_WSZ;
    float* gsm = sH;

    int bid = blockIdx.x;
    int dir = bid >> 6;
    int rem = bid & 63;
    int pch = rem >> 2;
    int jch = rem & 3;
    int p0 = pch * 128;
    int j0 = jch * 32;
    int barIdx = (pch * 2 + dir) * 32;

    const float* W = dir ? W1 : W0;
    const float* xp = dir ? g_xp1 : g_xp0;
    float* cD = g_cst + (size_t)dir * BN * 128;
    float* hsD = g_hsum + (size_t)dir * BN * 128;

    int tid = threadIdx.x;
    int lane = tid & 31, warp = tid >> 5;
    int g = lane >> 2, tig = lane & 3;
    int wm = warp & 3, wn = warp >> 2;

    // ---- stage W hi/lo ONCE ----
    {
        int row = tid >> 2;
        int gg = row >> 5, jr = row & 31;
        int kq = (tid & 3) * 32;
        const float* wrow = W + (size_t)(gg * 128 + j0 + jr) * 128 + kq;
        int so = row * S5_WST + kq;
#pragma unroll
        for (int q = 0; q < 8; q++) {
            float4 v = *(const float4*)(wrow + q * 4);
            float4 h4, l4;
            h4.x = tf32_rna(v.x); l4.x = tf32_rna(v.x - h4.x);
            h4.y = tf32_rna(v.y); l4.y = tf32_rna(v.y - h4.y);
            h4.z = tf32_rna(v.z); l4.z = tf32_rna(v.z - h4.z);
            h4.w = tf32_rna(v.w); l4.w = tf32_rna(v.w - h4.w);
            *(float4*)&sWh[so + q * 4] = h4;
            *(float4*)&sWl[so + q * 4] = l4;
        }
    }
    __syncthreads();

    int srow = tid >> 2;
    int sq8 = (tid & 3) * 8;

    for (int s = 0; s < TSEQ; s++) {
        int t = dir ? (TSEQ - 1 - s) : s;

        // ---- prefetch xp for this step's epilogue (hidden under mma) ----
        float4 xv[8];
        {
            size_t xbase = (size_t)t * BN * 512;
#pragma unroll
            for (int i = 0; i < 8; i++) {
                int pj = tid + i * 512;
                int pp = pj >> 5, jj = pj & 31;
                xv[i] = *(const float4*)(xp + xbase + (size_t)(p0 + pp) * 512
                                         + (j0 + jj) * 4);
            }
        }

        if (s > 0) {
            const float* hIn = g_hbuf[s & 1] + (size_t)dir * BN * 128;
            const float* aRow = hIn + (size_t)(p0 + srow) * 128 + sq8;
            int hso = srow * S5_HST + sq8;

            float acc[2][4][4];
#pragma unroll
            for (int i = 0; i < 2; i++)
#pragma unroll
                for (int j = 0; j < 4; j++)
#pragma unroll
                    for (int c = 0; c < 4; c++) acc[i][j][c] = 0.0f;

            {
                float* dh = sH + 0 * S5_HBUF;
                float* dl = dh + 128 * S5_HST;
#pragma unroll
                for (int q = 0; q < 2; q++) {
                    float4 v = *(const float4*)(aRow + q * 4);
                    float4 h4, l4;
                    h4.x = tf32_rna(v.x); l4.x = tf32_rna(v.x - h4.x);
                    h4.y = tf32_rna(v.y); l4.y = tf32_rna(v.y - h4.y);
                    h4.z = tf32_rna(v.z); l4.z = tf32_rna(v.z - h4.z);
                    h4.w = tf32_rna(v.w); l4.w = tf32_rna(v.w - h4.w);
                    *(float4*)&dh[hso + q * 4] = h4;
                    *(float4*)&dl[hso + q * 4] = l4;
                }
            }
            __syncthreads();

#pragma unroll
            for (int kc = 0; kc < 4; kc++) {
                int cur = kc & 1;
                float4 pre[2];
                if (kc < 3) {
#pragma unroll
                    for (int q = 0; q < 2; q++)
                        pre[q] = *(const float4*)(aRow + (kc + 1) * 32 + q * 4);
                }
                const float* bh_base = sWh;
                const float* bl_base = sWl;
                const float* ah_base = sH + cur * S5_HBUF;
                const float* al_base = ah_base + 128 * S5_HST;
#pragma unroll
                for (int kt = 0; kt < 4; kt++) {
                    int kbW = kc * 32 + kt * 8;
                    int kbH = kt * 8;
                    u32 bh[4][2], bl[4][2];
#pragma unroll
                    for (int nt = 0; nt < 4; nt++) {
                        int br = (wn * 32 + nt * 8 + g) * S5_WST + kbW;
                        bh[nt][0] = __float_as_uint(bh_base[br + tig]);
                        bh[nt][1] = __float_as_uint(bh_base[br + tig + 4]);
                        bl[nt][0] = __float_as_uint(bl_base[br + tig]);
                        bl[nt][1] = __float_as_uint(bl_base[br + tig + 4]);
                    }
#pragma unroll
                    for (int mt = 0; mt < 2; mt++) {
                        int ar0 = (wm * 32 + mt * 16 + g) * S5_HST + kbH;
                        int ar1 = ar0 + 8 * S5_HST;
                        u32 ah[4], al[4];
                        ah[0] = __float_as_uint(ah_base[ar0 + tig]);
                        ah[1] = __float_as_uint(ah_base[ar1 + tig]);
                        ah[2] = __float_as_uint(ah_base[ar0 + tig + 4]);
                        ah[3] = __float_as_uint(ah_base[ar1 + tig + 4]);
                        al[0] = __float_as_uint(al_base[ar0 + tig]);
                        al[1] = __float_as_uint(al_base[ar1 + tig]);
                        al[2] = __float_as_uint(al_base[ar0 + tig + 4]);
                        al[3] = __float_as_uint(al_base[ar1 + tig + 4]);
#pragma unroll
                        for (int nt = 0; nt < 4; nt++) {
                            mma_tf32(acc[mt][nt], ah, bh[nt]);
                            mma_tf32(acc[mt][nt], al, bh[nt]);
                            mma_tf32(acc[mt][nt], ah, bl[nt]);
                        }
                    }
                }
                if (kc < 3) {
                    float* dh = sH + (1 - cur) * S5_HBUF;
                    float* dl = dh + 128 * S5_HST;
#pragma unroll
                    for (int q = 0; q < 2; q++) {
                        float4 v = pre[q];
                        float4 h4, l4;
                        h4.x = tf32_rna(v.x); l4.x = tf32_rna(v.x - h4.x);
                        h4.y = tf32_rna(v.y); l4.y = tf32_rna(v.y - h4.y);
                        h4.z = tf32_rna(v.z); l4.z = tf32_rna(v.z - h4.z);
                        h4.w = tf32_rna(v.w); l4.w = tf32_rna(v.w - h4.w);
                        *(float4*)&dh[hso + q * 4] = h4;
                        *(float4*)&dl[hso + q * 4] = l4;
                    }
                }
                __syncthreads();
            }

#pragma unroll
            for (int mt = 0; mt < 2; mt++) {
                int r0 = wm * 32 + mt * 16 + g;
#pragma unroll
                for (int nt = 0; nt < 4; nt++) {
                    int col = wn * 32 + nt * 8 + 2 * tig;
                    *(float2*)&gsm[r0 * 132 + col] =
                        make_float2(acc[mt][nt][0], acc[mt][nt][1]);
                    *(float2*)&gsm[(r0 + 8) * 132 + col] =
                        make_float2(acc[mt][nt][2], acc[mt][nt][3]);
                }
            }
            __syncthreads();
        }

        // ---- fused LSTM epilogue ----
        float* hOut = g_hbuf[(s + 1) & 1] + (size_t)dir * BN * 128;
#pragma unroll
        for (int i = 0; i < 8; i++) {
            int pj = tid + i * 512;
            int pp = pj >> 5, jj = pj & 31;
            int p = p0 + pp;
            int j = j0 + jj;
            float gi = xv[i].x, gf = xv[i].y, gg2 = xv[i].z, go = xv[i].w;
            if (s > 0) {
                gi  += gsm[pp * 132 + jj];
                gf  += gsm[pp * 132 + 32 + jj];
                gg2 += gsm[pp * 132 + 64 + jj];
                go  += gsm[pp * 132 + 96 + jj];
            }
            size_t hidx = (size_t)p * 128 + j;
            float cold = (s == 0) ? 0.0f : cD[hidx];
            float cn = sigf(gf) * cold + sigf(gi) * tanhfast(gg2);
            float hn = sigf(go) * tanhfast(cn);
            if (s == TSEQ - 1) {
                float hs = hsD[hidx] + hn;
                g_sentpres[(size_t)p * 256 + dir * 128 + j] =
                    tanhfast(hs * (1.0f / 50.0f));
            } else {
                cD[hidx] = cn;
                hOut[hidx] = hn;
                hsD[hidx] = (s == 0) ? hn : (hsD[hidx] + hn);
            }
        }

        if (s < TSEQ - 1) {
            __syncthreads();
            if (tid == 0) {
                __threadfence();
                atomicAdd(&g_sbar[barIdx], 1);
                int target = 4 * (s + 1);
                while (*(volatile int*)&g_sbar[barIdx] < target) { }
                __threadfence();
            }
            __syncthreads();
        }
    }

    __syncthreads();
    if (tid == 0) {
        int old = atomicAdd(&g_sdone[barIdx], 1);
        if (old == 3) {
            g_sbar[barIdx] = 0;
            __threadfence();
            g_sdone[barIdx] = 0;
        }
    }
}

// ============================================================
// Dual-half GEMM with f32x2 (modes 1-4).
// MODE 1 writes gate-interleaved txp: [n][b][j*4+gate].
// ============================================================
template <int MODE>
__global__ void __launch_bounds__(256) gemm_dual(
    const float* __restrict__ Aparam, int M, int K, int NB,
    const float* __restrict__ B0, const float* __restrict__ B1,
    const float* __restrict__ bias0, const float* __restrict__ bias1,
    float* __restrict__ outParam)
{
    __shared__ __align__(16) u64 As2[8][128];
    __shared__ __align__(16) float Bs[8][128];

    const float* A;
    if (MODE == 1 || MODE == 2) A = g_sentpres;
    else if (MODE == 3) A = g_tag_out;
    else A = g_agg;
    (void)Aparam;

    int hsel = (blockIdx.y * 128) / NB;
    int g0 = blockIdx.y * 128 - hsel * NB;
    int m0 = blockIdx.x * 128;

    const float* B = hsel ? B1 : B0;
    const float* bias = hsel ? bias1 : bias0;

    float* out;
    if (MODE == 1) out = hsel ? g_txp1 : g_txp0;
    else if (MODE == 2 || MODE == 3) out = hsel ? g_k : g_q;
    else out = outParam;

    int tid = threadIdx.x;
    int tx = tid & 15;
    int ty = tid >> 4;
    int lr = tid >> 1;
    int lc4 = tid & 1;

    u64 acc2[8][4];
#pragma unroll
    for (int i = 0; i < 8; i++)
#pragma unroll
        for (int j = 0; j < 4; j++) acc2[i][j] = 0ULL;

    int KT = K / 8;
    const float* aPtr = A + (size_t)(m0 + lr) * K + lc4 * 4;
    const float* bPtr = B + (size_t)(g0 + lr) * K + lc4 * 4;
    float4 av = *(const float4*)(aPtr);
    float4 bv = *(const float4*)(bPtr);

    for (int kt = 0; kt < KT; kt++) {
        As2[lc4 * 4 + 0][lr] = pk2(av.x, av.x);
        As2[lc4 * 4 + 1][lr] = pk2(av.y, av.y);
        As2[lc4 * 4 + 2][lr] = pk2(av.z, av.z);
        As2[lc4 * 4 + 3][lr] = pk2(av.w, av.w);
        Bs[lc4 * 4 + 0][lr] = bv.x; Bs[lc4 * 4 + 1][lr] = bv.y;
        Bs[lc4 * 4 + 2][lr] = bv.z; Bs[lc4 * 4 + 3][lr] = bv.w;
        __syncthreads();
        if (kt + 1 < KT) {
            av = *(const float4*)(aPtr + (kt + 1) * 8);
            bv = *(const float4*)(bPtr + (kt + 1) * 8);
        }
#pragma unroll
        for (int kk = 0; kk < 8; kk++) {
            u64 b2[4];
#pragma unroll
            for (int jq = 0; jq < 4; jq++)
                b2[jq] = *(const u64*)&Bs[kk][2 * (tx + 16 * jq)];
            u64 a2[8];
#pragma unroll
            for (int i = 0; i < 8; i++) a2[i] = As2[kk][ty * 8 + i];
#pragma unroll
            for (int i = 0; i < 8; i++)
#pragma unroll
                for (int jq = 0; jq < 4; jq++)
                    fma2(acc2[i][jq], a2[i], b2[jq]);
        }
        __syncthreads();
    }

#pragma unroll
    for (int i = 0; i < 8; i++) {
        int m = m0 + ty * 8 + i;
        size_t rowbase;
        if (MODE == 1) {
            int b = m >> 6; int n = m & 63;
            rowbase = ((size_t)n * BB + b) * 512;
        } else {
            rowbase = (size_t)m * 256;
        }
#pragma unroll
        for (int jq = 0; jq < 4; jq++) {
            int gcol = g0 + 2 * (tx + 16 * jq);
            float lo, hi;
            up2(acc2[i][jq], lo, hi);
            float2 bb = *(const float2*)(bias + gcol);
            float o0 = lo + bb.x;
            float o1 = hi + bb.y;
            if (MODE == 1) {
                int gate = gcol >> 7;
                int jl = gcol & 127;
                out[rowbase + jl * 4 + gate] = o0;
                out[rowbase + (jl + 1) * 4 + gate] = o1;
            } else {
                if (MODE == 4) { o0 = fmaxf(o0, 0.f); o1 = fmaxf(o1, 0.f); }
                *(float2*)(out + rowbase + gcol) = make_float2(o0, o1);
            }
        }
    }
}

// ============================================================
// Persistent tag BiLSTM v3: TENSOR CORES (3xTF32),
// xp prefetched at step start (LDG.128, gate-interleaved).
// ============================================================
#define TG2_WST  132
#define TG2_HST  132
#define TG2_WSZ  (64 * TG2_WST)
#define TG2_HSZ  (32 * TG2_HST)
#define TG2_SMEM ((2 * TG2_WSZ + 2 * TG2_HSZ + 32 * 68) * 4)

__global__ void __launch_bounds__(256) tag_persistent_tc(
    const float* __restrict__ W0, const float* __restrict__ W1)
{
    extern __shared__ __align__(16) float tg2[];
    float* sWh = tg2;
    float* sWl = tg2 + TG2_WSZ;
    float* sHh = tg2 + 2 * TG2_WSZ;
    float* sHl = sHh + TG2_HSZ;
    float* gsm = sHl + TG2_HSZ;

    int dir = blockIdx.x >> 3;
    int jc = blockIdx.x & 7;
    int j0 = jc * 16;
    const float* W = dir ? W1 : W0;
    const float* xp = dir ? g_txp1 : g_txp0;

    int tid = threadIdx.x;
    int lane = tid & 31, warp = tid >> 5;
    int g = lane >> 2, tig = lane & 3;

    {
        int row = tid >> 2;
        int gg = row >> 4, jr = row & 15;
        int kq = (tid & 3) * 32;
        const float* wrow = W + (size_t)(gg * 128 + j0 + jr) * 128 + kq;
        int so = row * TG2_WST + kq;
#pragma unroll
        for (int q = 0; q < 8; q++) {
            float4 v = *(const float4*)(wrow + q * 4);
            float4 h4, l4;
            h4.x = tf32_rna(v.x); l4.x = tf32_rna(v.x - h4.x);
            h4.y = tf32_rna(v.y); l4.y = tf32_rna(v.y - h4.y);
            h4.z = tf32_rna(v.z); l4.z = tf32_rna(v.z - h4.z);
            h4.w = tf32_rna(v.w); l4.w = tf32_rna(v.w - h4.w);
            *(float4*)&sWh[so + q * 4] = h4;
            *(float4*)&sWl[so + q * 4] = l4;
        }
    }
    __syncthreads();

    float creg[2] = {0.f, 0.f};
    int* bar = &g_tbar2[dir * 32];

    for (int s = 0; s < NSEQ; s++) {
        int t = dir ? (NSEQ - 1 - s) : s;

        // prefetch xp for this step's epilogue
        float4 xv[2];
#pragma unroll
        for (int u = 0; u < 2; u++) {
            int idx = tid + u * 256;
            int b = idx >> 4, jj = idx & 15;
            xv[u] = *(const float4*)(xp + ((size_t)t * BB + b) * 512
                                     + (j0 + jj) * 4);
        }

        if (s > 0) {
            const float* hIn = g_thbuf[s & 1] + (size_t)dir * BB * 128;
            {
                int row = tid >> 3;
                int kq = (tid & 7) * 16;
                const float* hrow = hIn + (size_t)row * 128 + kq;
                int so = row * TG2_HST + kq;
#pragma unroll
                for (int q = 0; q < 4; q++) {
                    float4 v = *(const float4*)(hrow + q * 4);
                    float4 h4, l4;
                    h4.x = tf32_rna(v.x); l4.x = tf32_rna(v.x - h4.x);
                    h4.y = tf32_rna(v.y); l4.y = tf32_rna(v.y - h4.y);
                    h4.z = tf32_rna(v.z); l4.z = tf32_rna(v.z - h4.z);
                    h4.w = tf32_rna(v.w); l4.w = tf32_rna(v.w - h4.w);
                    *(float4*)&sHh[so + q * 4] = h4;
                    *(float4*)&sHl[so + q * 4] = l4;
                }
            }
            __syncthreads();

            float acc[2][4];
#pragma unroll
            for (int mt = 0; mt < 2; mt++)
#pragma unroll
                for (int c = 0; c < 4; c++) acc[mt][c] = 0.0f;

#pragma unroll
            for (int kt = 0; kt < 16; kt++) {
                int kb = kt * 8;
                int br = (warp * 8 + g) * TG2_WST + kb;
                u32 bh[2], bl[2];
                bh[0] = __float_as_uint(sWh[br + tig]);
                bh[1] = __float_as_uint(sWh[br + tig + 4]);
                bl[0] = __float_as_uint(sWl[br + tig]);
                bl[1] = __float_as_uint(sWl[br + tig + 4]);
#pragma unroll
                for (int mt = 0; mt < 2; mt++) {
                    int ar0 = (mt * 16 + g) * TG2_HST + kb;
                    int ar1 = ar0 + 8 * TG2_HST;
                    u32 ah[4], al[4];
                    ah[0] = __float_as_uint(sHh[ar0 + tig]);
                    ah[1] = __float_as_uint(sHh[ar1 + tig]);
                    ah[2] = __float_as_uint(sHh[ar0 + tig + 4]);
                    ah[3] = __float_as_uint(sHh[ar1 + tig + 4]);
                    al[0] = __float_as_uint(sHl[ar0 + tig]);
                    al[1] = __float_as_uint(sHl[ar1 + tig]);
                    al[2] = __float_as_uint(sHl[ar0 + tig + 4]);
                    al[3] = __float_as_uint(sHl[ar1 + tig + 4]);
                    mma_tf32(acc[mt], ah, bh);
                    mma_tf32(acc[mt], al, bh);
                    mma_tf32(acc[mt], ah, bl);
                }
            }

#pragma unroll
            for (int mt = 0; mt < 2; mt++) {
                int r0 = mt * 16 + g;
                int col = warp * 8 + 2 * tig;
                *(float2*)&gsm[r0 * 68 + col] = make_float2(acc[mt][0], acc[mt][1]);
                *(float2*)&gsm[(r0 + 8) * 68 + col] = make_float2(acc[mt][2], acc[mt][3]);
            }
            __syncthreads();
        }

        float* hOut = g_thbuf[(s + 1) & 1] + (size_t)dir * BB * 128;
#pragma unroll
        for (int u = 0; u < 2; u++) {
            int idx = tid + u * 256;
            int b = idx >> 4, jj = idx & 15;
            float gi = xv[u].x, gf = xv[u].y, gg2 = xv[u].z, go = xv[u].w;
            if (s > 0) {
                gi  += gsm[b * 68 + jj];
                gf  += gsm[b * 68 + 16 + jj];
                gg2 += gsm[b * 68 + 32 + jj];
                go  += gsm[b * 68 + 48 + jj];
            }
            float cn = sigf(gf) * creg[u] + sigf(gi) * tanhfast(gg2);
            float hn = sigf(go) * tanhfast(cn);
            creg[u] = cn;
            hOut[(size_t)b * 128 + j0 + jj] = hn;
            g_tag_out[((size_t)b * NSEQ + t) * 256 + dir * 128 + j0 + jj] = tanhfast(hn);
        }

        if (s < NSEQ - 1) {
            __syncthreads();
            if (tid == 0) {
                __threadfence();
                atomicAdd(bar, 1);
                int target = 8 * (s + 1);
                while (*(volatile int*)bar < target) { }
                __threadfence();
            }
            __syncthreads();
        }
    }

    __syncthreads();
    if (tid == 0) {
        int old = atomicAdd(&g_tdone2[dir * 32], 1);
        if (old == 7) {
            g_tbar2[dir * 32] = 0;
            __threadfence();
            g_tdone2[dir * 32] = 0;
        }
    }
}

// ---------------- SPP ----------------
__global__ void __launch_bounds__(256) spp_kernel(int which) {
    int b = blockIdx.x;
    int tid = threadIdx.x;
    __shared__ float qs[64][33];
    __shared__ float ks[64][33];
    __shared__ float segs[64][8];

    float acc[16];
#pragma unroll
    for (int i = 0; i < 16; i++) acc[i] = 0.0f;
    int n = tid >> 2;
    int mBase = (tid & 3) * 16;

    for (int d0 = 0; d0 < 256; d0 += 32) {
        __syncthreads();
        for (int idx = tid; idx < 64 * 32; idx += 256) {
            int r = idx >> 5, cc = idx & 31;
            size_t gi = ((size_t)(b * 64 + r)) * 256 + d0 + cc;
            qs[r][cc] = g_q[gi];
            ks[r][cc] = g_k[gi];
        }
        __syncthreads();
#pragma unroll 4
        for (int dd = 0; dd < 32; dd++) {
            float qv = qs[n][dd];
#pragma unroll
            for (int mm = 0; mm < 16; mm++)
                acc[mm] += qv * ks[mBase + mm][dd];
        }
    }
    float s8a = -3.4e38f, s8b = -3.4e38f;
#pragma unroll
    for (int mm = 0; mm < 8; mm++)  s8a = fmaxf(s8a, acc[mm]);
#pragma unroll
    for (int mm = 8; mm < 16; mm++) s8b = fmaxf(s8b, acc[mm]);
    segs[n][(tid & 3) * 2 + 0] = s8a * 0.0625f;
    segs[n][(tid & 3) * 2 + 1] = s8b * 0.0625f;
    __syncthreads();

    if (tid < 64) {
        float e[8];
#pragma unroll
        for (int i = 0; i < 8; i++) e[i] = segs[tid][i];
        float q4[4], h2[2];
#pragma unroll
        for (int i = 0; i < 4; i++) q4[i] = fmaxf(e[2 * i], e[2 * i + 1]);
        h2[0] = fmaxf(q4[0], q4[1]);
        h2[1] = fmaxf(q4[2], q4[3]);
        float a1 = fmaxf(h2[0], h2[1]);
        float* o = (which ? g_roleFt : g_sentFt) + (size_t)(b * 64 + tid) * 15;
        o[0] = a1;
        o[1] = h2[0]; o[2] = h2[1];
#pragma unroll
        for (int i = 0; i < 4; i++) o[3 + i] = q4[i];
#pragma unroll
        for (int i = 0; i < 8; i++) o[7 + i] = e[i];
    }
}

// ---------------- GCN pre ----------------
__global__ void __launch_bounds__(256) gcn_pre() {
    int b = blockIdx.x;
    int tid = threadIdx.x;
    __shared__ float cosm[64][65];
    __shared__ float xs[64][33];
    __shared__ float inv[64];

    if (tid < 64) {
        const float* xr = g_tag_out + (size_t)(b * 64 + tid) * 256;
        float s = 0.0f;
        for (int d = 0; d < 256; d++) { float v = xr[d]; s += v * v; }
        inv[tid] = 1.0f / (sqrtf(s) + 1e-8f);
    }

    float acc[16];
#pragma unroll
    for (int i = 0; i < 16; i++) acc[i] = 0.0f;
    int n = tid >> 2;
    int mBase = (tid & 3) * 16;

    for (int d0 = 0; d0 < 256; d0 += 32) {
        __syncthreads();
        for (int idx = tid; idx < 64 * 32; idx += 256) {
            int r = idx >> 5, cc = idx & 31;
            xs[r][cc] = g_tag_out[((size_t)(b * 64 + r)) * 256 + d0 + cc];
        }
        __syncthreads();
#pragma unroll 4
        for (int dd = 0; dd < 32; dd++) {
            float xv = xs[n][dd];
#pragma unroll
            for (int mm = 0; mm < 16; mm++)
                acc[mm] += xv * xs[mBase + mm][dd];
        }
    }
#pragma unroll
    for (int mm = 0; mm < 16; mm++)
        cosm[n][mBase + mm] = acc[mm] * inv[n] * inv[mBase + mm];

    int ddBase = (tid & 3) * 8;
    for (int d0 = 0; d0 < 256; d0 += 32) {
        __syncthreads();
        for (int idx = tid; idx < 64 * 32; idx += 256) {
            int r = idx >> 5, cc = idx & 31;
            xs[r][cc] = g_tag_out[((size_t)(b * 64 + r)) * 256 + d0 + cc];
        }
        __syncthreads();
        float r8[8];
#pragma unroll
        for (int i = 0; i < 8; i++) r8[i] = 0.0f;
        for (int m = 0; m < 64; m++) {
            float cv = cosm[n][m];
#pragma unroll
            for (int i = 0; i < 8; i++) r8[i] += cv * xs[m][ddBase + i];
        }
#pragma unroll
        for (int i = 0; i < 8; i++) {
            float v = (r8[i] + 2.0f * xs[n][ddBase + i]) * (1.0f / 66.0f);
            g_agg[(size_t)(b * 64 + n) * 256 + d0 + ddBase + i] = v;
        }
    }
}

// ---------------- classifier + log_softmax ----------------
__global__ void __launch_bounds__(256) cls_kernel(
    const float* __restrict__ W, const float* __restrict__ bias,
    float* __restrict__ out)
{
    __shared__ float Wsh[8][288];
    __shared__ float bsh[8];
    __shared__ float ftile[256][33];

    int tid = threadIdx.x;
    for (int i = tid; i < 8 * 286; i += 256) Wsh[i / 286][i % 286] = W[i];
    if (tid < 8) bsh[tid] = bias[tid];
    __syncthreads();

    int p0 = blockIdx.x * 256;
    int p = p0 + tid;
    float z[8];
#pragma unroll
    for (int c = 0; c < 8; c++) z[c] = bsh[c];

    for (int d0 = 0; d0 < 256; d0 += 32) {
        __syncthreads();
        for (int idx = tid; idx < 256 * 32; idx += 256) {
            int r = idx >> 5, cc = idx & 31;
            ftile[r][cc] = g_tag_out[(size_t)(p0 + r) * 256 + d0 + cc];
        }
        __syncthreads();
#pragma unroll 4
        for (int dd = 0; dd < 32; dd++) {
            float f = ftile[tid][dd];
#pragma unroll
            for (int c = 0; c < 8; c++) z[c] += f * Wsh[c][d0 + dd];
        }
    }
#pragma unroll
    for (int d = 0; d < 15; d++) {
        float f = g_sentFt[(size_t)p * 15 + d];
#pragma unroll
        for (int c = 0; c < 8; c++) z[c] += f * Wsh[c][256 + d];
    }
#pragma unroll
    for (int d = 0; d < 15; d++) {
        float f = g_roleFt[(size_t)p * 15 + d];
#pragma unroll
        for (int c = 0; c < 8; c++) z[c] += f * Wsh[c][271 + d];
    }
    float m = z[0];
#pragma unroll
    for (int c = 1; c < 8; c++) m = fmaxf(m, z[c]);
    float se = 0.0f;
#pragma unroll
    for (int c = 0; c < 8; c++) se += expf(z[c] - m);
    float lse = m + logf(se);
#pragma unroll
    for (int c = 0; c < 8; c++) out[(size_t)p * 8 + c] = z[c] - lse;
}

// ============================================================
extern "C" void kernel_launch(void* const* d_in, const int* in_sizes, int n_in,
                              void* d_out, int out_size)
{
    (void)in_sizes; (void)n_in; (void)out_size;
    const float* documents = (const float*)d_in[0];
    const float* sw_ih_f = (const float*)d_in[1];
    const float* sw_hh_f = (const float*)d_in[2];
    const float* sb_f    = (const float*)d_in[3];
    const float* sw_ih_b = (const float*)d_in[4];
    const float* sw_hh_b = (const float*)d_in[5];
    const float* sb_b    = (const float*)d_in[6];
    const float* sf_Wq   = (const float*)d_in[7];
    const float* sf_bq   = (const float*)d_in[8];
    const float* sf_Wk   = (const float*)d_in[9];
    const float* sf_bk   = (const float*)d_in[10];
    const float* rf_Wq   = (const float*)d_in[11];
    const float* rf_bq   = (const float*)d_in[12];
    const float* rf_Wk   = (const float*)d_in[13];
    const float* rf_bk   = (const float*)d_in[14];
    const float* tw_ih_f = (const float*)d_in[15];
    const float* tw_hh_f = (const float*)d_in[16];
    const float* tb_f    = (const float*)d_in[17];
    const float* tw_ih_b = (const float*)d_in[18];
    const float* tw_hh_b = (const float*)d_in[19];
    const float* tb_b    = (const float*)d_in[20];
    const float* sage_W  = (const float*)d_in[21];
    const float* sage_b  = (const float*)d_in[22];
    const float* cls_W   = (const float*)d_in[23];
    const float* cls_b   = (const float*)d_in[24];
    float* out = (float*)d_out;

    cudaFuncSetAttribute(lstm_sent5, cudaFuncAttributeMaxDynamicSharedMemorySize, S5_SMEM);
    cudaFuncSetAttribute(tag_persistent_tc, cudaFuncAttributeMaxDynamicSharedMemorySize, TG2_SMEM);

    // 1) sentence BiLSTM input projection (gate-interleaved xp out)
    gemm_inproj_tc<<<dim3(800, 8), 256>>>(documents, sw_ih_f, sw_ih_b, sb_f, sb_b);
    // 2) sentence recurrence: persistent tensor-core kernel, 512 threads
    lstm_sent5<<<128, 512, S5_SMEM>>>(sw_hh_f, sw_hh_b);
    // 3) tag BiLSTM input projection (gate-interleaved txp out)
    gemm_dual<1><<<dim3(16, 8), 256>>>(nullptr, 2048, 256, 512,
                                       tw_ih_f, tw_ih_b, tb_f, tb_b, nullptr);
    // 4) tag recurrence: persistent tensor-core kernel
    tag_persistent_tc<<<16, 256, TG2_SMEM>>>(tw_hh_f, tw_hh_b);
    // 5) SPP on sentpres -> sentFt
    gemm_dual<2><<<dim3(16, 4), 256>>>(nullptr, 2048, 256, 256,
                                       sf_Wq, sf_Wk, sf_bq, sf_bk, nullptr);
    spp_kernel<<<32, 256>>>(0);
    // 6) SPP on tag_out -> roleFt
    gemm_dual<3><<<dim3(16, 4), 256>>>(nullptr, 2048, 256, 256,
                                       rf_Wq, rf_Wk, rf_bq, rf_bk, nullptr);
    spp_kernel<<<32, 256>>>(1);
    // 7) GCN
    gcn_pre<<<32, 256>>>();
    gemm_dual<4><<<dim3(16, 2), 256>>>(nullptr, 2048, 256, 256,
                                       sage_W, sage_W, sage_b, sage_b, out + 16384);
    // 8) classifier + log_softmax
    cls_kernel<<<8, 256>>>(cls_W, cls_b, out);
}

// round 14
// speedup vs baseline: 1.1720x; 1.1720x over previous
#include <cuda_runtime.h>
#include <math.h>
#include <stdint.h>

typedef unsigned long long u64;
typedef unsigned int u32;

// ---------------- problem constants ----------------
#define BN   2048
#define TSEQ 50
#define NSEQ 64
#define BB   32

// g_xp layout: [t][p][gate*128+j] (contiguous — R12 proven)
// g_txp layout: [n][b][j*4+gate]  (gate-interleaved — R13 proven for tag)

// ---------------- device scratch ----------------
__device__ float g_xp0[(size_t)TSEQ * BN * 512];
__device__ float g_xp1[(size_t)TSEQ * BN * 512];
__device__ float g_hbuf[2][2 * BN * 128];
__device__ float g_cst[2 * BN * 128];
__device__ float g_hsum[2 * BN * 128];
__device__ float g_sentpres[(size_t)BN * 256];
__device__ float g_txp0[(size_t)NSEQ * BB * 512];
__device__ float g_txp1[(size_t)NSEQ * BB * 512];
__device__ float g_thbuf[2][2 * BB * 128];
__device__ float g_tag_out[(size_t)BN * 256];
__device__ float g_q[(size_t)BN * 256];
__device__ float g_k[(size_t)BN * 256];
__device__ float g_sentFt[(size_t)BN * 15];
__device__ float g_roleFt[(size_t)BN * 15];
__device__ float g_agg[(size_t)BN * 256];
__device__ int g_tbar2[2 * 32];
__device__ int g_tdone2[2 * 32];
__device__ int g_sbar[32 * 32];
__device__ int g_sdone[32 * 32];

// ---------------- f32x2 helpers ----------------
__device__ __forceinline__ u64 pk2(float lo, float hi) {
    u64 r; asm("mov.b64 %0, {%1, %2};" : "=l"(r) : "f"(lo), "f"(hi)); return r;
}
__device__ __forceinline__ void up2(u64 v, float& lo, float& hi) {
    asm("mov.b64 {%0, %1}, %2;" : "=f"(lo), "=f"(hi) : "l"(v));
}
__device__ __forceinline__ void fma2(u64& d, u64 a, u64 b) {
    asm("fma.rn.f32x2 %0, %1, %2, %0;" : "+l"(d) : "l"(a), "l"(b));
}

// ---------------- tf32 helpers ----------------
__device__ __forceinline__ float tf32_rna(float x) {
    u32 u; asm("cvt.rna.tf32.f32 %0, %1;" : "=r"(u) : "f"(x));
    return __uint_as_float(u);
}
__device__ __forceinline__ void mma_tf32(float* d, const u32* a, const u32* b) {
    asm("mma.sync.aligned.m16n8k8.row.col.f32.tf32.tf32.f32 "
        "{%0,%1,%2,%3},{%4,%5,%6,%7},{%8,%9},{%0,%1,%2,%3};"
        : "+f"(d[0]), "+f"(d[1]), "+f"(d[2]), "+f"(d[3])
        : "r"(a[0]), "r"(a[1]), "r"(a[2]), "r"(a[3]), "r"(b[0]), "r"(b[1]));
}

// ---------------- fast math ----------------
__device__ __forceinline__ float sigf(float x) {
    x = fminf(fmaxf(x, -30.f), 30.f);
    return __fdividef(1.f, 1.f + __expf(-x));
}
__device__ __forceinline__ float tanhfast(float x) {
    x = fminf(fmaxf(x, -15.f), 15.f);
    return __fdividef(2.f, 1.f + __expf(-2.f * x)) - 1.f;
}

// ============================================================
// K1: sentence input projection with tensor cores (3xTF32).
// R12 version: contiguous xp output (coalesced float2 stores).
// ============================================================
#define K1P 12
__global__ void __launch_bounds__(256) gemm_inproj_tc(
    const float* __restrict__ A,
    const float* __restrict__ B0, const float* __restrict__ B1,
    const float* __restrict__ bias0, const float* __restrict__ bias1)
{
    __shared__ float sAh[2][128 * K1P], sAl[2][128 * K1P];
    __shared__ float sBh[2][128 * K1P], sBl[2][128 * K1P];

    int m0 = blockIdx.x * 128;
    int nb = blockIdx.y;
    int dir = nb >> 2;
    int n0 = (nb & 3) * 128;
    const float* Bw = dir ? B1 : B0;
    const float* bias = dir ? bias1 : bias0;
    float* out = dir ? g_xp1 : g_xp0;

    int tid = threadIdx.x;
    int lane = tid & 31, warp = tid >> 5;
    int g = lane >> 2, tig = lane & 3;
    int wm = warp & 1, wn = warp >> 1;

    int srow = tid >> 1, shalf = tid & 1;
    const float* aP = A + (size_t)(m0 + srow) * 200 + shalf * 4;
    const float* bP = Bw + (size_t)(n0 + srow) * 200 + shalf * 4;

    float acc[4][4][4];
#pragma unroll
    for (int i = 0; i < 4; i++)
#pragma unroll
        for (int j = 0; j < 4; j++)
#pragma unroll
            for (int c = 0; c < 4; c++) acc[i][j][c] = 0.0f;

    float4 av = *(const float4*)aP;
    float4 bv = *(const float4*)bP;

    int soff = srow * K1P + shalf * 4;
#define K1_STAGE(buf, a4, b4) do {                                          \
        float4 _h, _l;                                                      \
        _h.x = tf32_rna(a4.x); _l.x = tf32_rna(a4.x - _h.x);                \
        _h.y = tf32_rna(a4.y); _l.y = tf32_rna(a4.y - _h.y);                \
        _h.z = tf32_rna(a4.z); _l.z = tf32_rna(a4.z - _h.z);                \
        _h.w = tf32_rna(a4.w); _l.w = tf32_rna(a4.w - _h.w);                \
        *(float4*)&sAh[buf][soff] = _h;                                     \
        *(float4*)&sAl[buf][soff] = _l;                                     \
        _h.x = tf32_rna(b4.x); _l.x = tf32_rna(b4.x - _h.x);                \
        _h.y = tf32_rna(b4.y); _l.y = tf32_rna(b4.y - _h.y);                \
        _h.z = tf32_rna(b4.z); _l.z = tf32_rna(b4.z - _h.z);                \
        _h.w = tf32_rna(b4.w); _l.w = tf32_rna(b4.w - _h.w);                \
        *(float4*)&sBh[buf][soff] = _h;                                     \
        *(float4*)&sBl[buf][soff] = _l;                                     \
    } while (0)

    K1_STAGE(0, av, bv);
    __syncthreads();

    for (int kt = 0; kt < 25; kt++) {
        int cur = kt & 1;
        if (kt < 24) {
            av = *(const float4*)(aP + (kt + 1) * 8);
            bv = *(const float4*)(bP + (kt + 1) * 8);
        }
        u32 bh[4][2], bl[4][2];
#pragma unroll
        for (int nt = 0; nt < 4; nt++) {
            int br = (wn * 32 + nt * 8 + g) * K1P;
            bh[nt][0] = __float_as_uint(sBh[cur][br + tig]);
            bh[nt][1] = __float_as_uint(sBh[cur][br + tig + 4]);
            bl[nt][0] = __float_as_uint(sBl[cur][br + tig]);
            bl[nt][1] = __float_as_uint(sBl[cur][br + tig + 4]);
        }
#pragma unroll
        for (int mt = 0; mt < 4; mt++) {
            int ar0 = (wm * 64 + mt * 16 + g) * K1P;
            int ar1 = ar0 + 8 * K1P;
            u32 ah[4], al[4];
            ah[0] = __float_as_uint(sAh[cur][ar0 + tig]);
            ah[1] = __float_as_uint(sAh[cur][ar1 + tig]);
            ah[2] = __float_as_uint(sAh[cur][ar0 + tig + 4]);
            ah[3] = __float_as_uint(sAh[cur][ar1 + tig + 4]);
            al[0] = __float_as_uint(sAl[cur][ar0 + tig]);
            al[1] = __float_as_uint(sAl[cur][ar1 + tig]);
            al[2] = __float_as_uint(sAl[cur][ar0 + tig + 4]);
            al[3] = __float_as_uint(sAl[cur][ar1 + tig + 4]);
#pragma unroll
            for (int nt = 0; nt < 4; nt++) {
                mma_tf32(acc[mt][nt], ah, bh[nt]);
                mma_tf32(acc[mt][nt], al, bh[nt]);
                mma_tf32(acc[mt][nt], ah, bl[nt]);
            }
        }
        __syncthreads();
        if (kt < 24) {
            K1_STAGE((kt + 1) & 1, av, bv);
            __syncthreads();
        }
    }

#pragma unroll
    for (int mt = 0; mt < 4; mt++) {
#pragma unroll
        for (int nt = 0; nt < 4; nt++) {
            int col = n0 + wn * 32 + nt * 8 + 2 * tig;
            float b0v = __ldg(bias + col), b1v = __ldg(bias + col + 1);
            int r0 = m0 + wm * 64 + mt * 16 + g;
            int p0 = r0 / 50, t0 = r0 - p0 * 50;
            float2 o0 = make_float2(acc[mt][nt][0] + b0v, acc[mt][nt][1] + b1v);
            *(float2*)(out + ((size_t)t0 * BN + p0) * 512 + col) = o0;
            int r1 = r0 + 8;
            int p1 = r1 / 50, t1 = r1 - p1 * 50;
            float2 o1 = make_float2(acc[mt][nt][2] + b0v, acc[mt][nt][3] + b1v);
            *(float2*)(out + ((size_t)t1 * BN + p1) * 512 + col) = o1;
        }
    }
}

// ============================================================
// Sentence LSTM: PERSISTENT tensor-core recurrence, 512 threads.
// R12 version (contiguous xp reads in epilogue).
// ============================================================
#define S5_WST   132
#define S5_HST   36
#define S5_WSZ   (128 * S5_WST)
#define S5_HBUF  (2 * 128 * S5_HST)
#define S5_SMEM  ((2 * S5_WSZ + 2 * S5_HBUF) * 4)

__global__ void __launch_bounds__(512, 1) lstm_sent5(
    const float* __restrict__ W0, const float* __restrict__ W1)
{
    extern __shared__ __align__(16) float s5[];
    float* sWh = s5;
    float* sWl = s5 + S5_WSZ;
    float* sH  = s5 + 2 * S5_WSZ;
    float* gsm = sH;

    int bid = blockIdx.x;
    int dir = bid >> 6;
    int rem = bid & 63;
    int pch = rem >> 2;
    int jch = rem & 3;
    int p0 = pch * 128;
    int j0 = jch * 32;
    int barIdx = (pch * 2 + dir) * 32;

    const float* W = dir ? W1 : W0;
    const float* xp = dir ? g_xp1 : g_xp0;
    float* cD = g_cst + (size_t)dir * BN * 128;
    float* hsD = g_hsum + (size_t)dir * BN * 128;

    int tid = threadIdx.x;
    int lane = tid & 31, warp = tid >> 5;
    int g = lane >> 2, tig = lane & 3;
    int wm = warp & 3, wn = warp >> 2;

    {
        int row = tid >> 2;
        int gg = row >> 5, jr = row & 31;
        int kq = (tid & 3) * 32;
        const float* wrow = W + (size_t)(gg * 128 + j0 + jr) * 128 + kq;
        int so = row * S5_WST + kq;
#pragma unroll
        for (int q = 0; q < 8; q++) {
            float4 v = *(const float4*)(wrow + q * 4);
            float4 h4, l4;
            h4.x = tf32_rna(v.x); l4.x = tf32_rna(v.x - h4.x);
            h4.y = tf32_rna(v.y); l4.y = tf32_rna(v.y - h4.y);
            h4.z = tf32_rna(v.z); l4.z = tf32_rna(v.z - h4.z);
            h4.w = tf32_rna(v.w); l4.w = tf32_rna(v.w - h4.w);
            *(float4*)&sWh[so + q * 4] = h4;
            *(float4*)&sWl[so + q * 4] = l4;
        }
    }
    __syncthreads();

    int srow = tid >> 2;
    int sq8 = (tid & 3) * 8;

    for (int s = 0; s < TSEQ; s++) {
        int t = dir ? (TSEQ - 1 - s) : s;

        if (s > 0) {
            const float* hIn = g_hbuf[s & 1] + (size_t)dir * BN * 128;
            const float* aRow = hIn + (size_t)(p0 + srow) * 128 + sq8;
            int hso = srow * S5_HST + sq8;

            float acc[2][4][4];
#pragma unroll
            for (int i = 0; i < 2; i++)
#pragma unroll
                for (int j = 0; j < 4; j++)
#pragma unroll
                    for (int c = 0; c < 4; c++) acc[i][j][c] = 0.0f;

            {
                float* dh = sH + 0 * S5_HBUF;
                float* dl = dh + 128 * S5_HST;
#pragma unroll
                for (int q = 0; q < 2; q++) {
                    float4 v = *(const float4*)(aRow + q * 4);
                    float4 h4, l4;
                    h4.x = tf32_rna(v.x); l4.x = tf32_rna(v.x - h4.x);
                    h4.y = tf32_rna(v.y); l4.y = tf32_rna(v.y - h4.y);
                    h4.z = tf32_rna(v.z); l4.z = tf32_rna(v.z - h4.z);
                    h4.w = tf32_rna(v.w); l4.w = tf32_rna(v.w - h4.w);
                    *(float4*)&dh[hso + q * 4] = h4;
                    *(float4*)&dl[hso + q * 4] = l4;
                }
            }
            __syncthreads();

#pragma unroll
            for (int kc = 0; kc < 4; kc++) {
                int cur = kc & 1;
                float4 pre[2];
                if (kc < 3) {
#pragma unroll
                    for (int q = 0; q < 2; q++)
                        pre[q] = *(const float4*)(aRow + (kc + 1) * 32 + q * 4);
                }
                const float* bh_base = sWh;
                const float* bl_base = sWl;
                const float* ah_base = sH + cur * S5_HBUF;
                const float* al_base = ah_base + 128 * S5_HST;
#pragma unroll
                for (int kt = 0; kt < 4; kt++) {
                    int kbW = kc * 32 + kt * 8;
                    int kbH = kt * 8;
                    u32 bh[4][2], bl[4][2];
#pragma unroll
                    for (int nt = 0; nt < 4; nt++) {
                        int br = (wn * 32 + nt * 8 + g) * S5_WST + kbW;
                        bh[nt][0] = __float_as_uint(bh_base[br + tig]);
                        bh[nt][1] = __float_as_uint(bh_base[br + tig + 4]);
                        bl[nt][0] = __float_as_uint(bl_base[br + tig]);
                        bl[nt][1] = __float_as_uint(bl_base[br + tig + 4]);
                    }
#pragma unroll
                    for (int mt = 0; mt < 2; mt++) {
                        int ar0 = (wm * 32 + mt * 16 + g) * S5_HST + kbH;
                        int ar1 = ar0 + 8 * S5_HST;
                        u32 ah[4], al[4];
                        ah[0] = __float_as_uint(ah_base[ar0 + tig]);
                        ah[1] = __float_as_uint(ah_base[ar1 + tig]);
                        ah[2] = __float_as_uint(ah_base[ar0 + tig + 4]);
                        ah[3] = __float_as_uint(ah_base[ar1 + tig + 4]);
                        al[0] = __float_as_uint(al_base[ar0 + tig]);
                        al[1] = __float_as_uint(al_base[ar1 + tig]);
                        al[2] = __float_as_uint(al_base[ar0 + tig + 4]);
                        al[3] = __float_as_uint(al_base[ar1 + tig + 4]);
#pragma unroll
                        for (int nt = 0; nt < 4; nt++) {
                            mma_tf32(acc[mt][nt], ah, bh[nt]);
                            mma_tf32(acc[mt][nt], al, bh[nt]);
                            mma_tf32(acc[mt][nt], ah, bl[nt]);
                        }
                    }
                }
                if (kc < 3) {
                    float* dh = sH + (1 - cur) * S5_HBUF;
                    float* dl = dh + 128 * S5_HST;
#pragma unroll
                    for (int q = 0; q < 2; q++) {
                        float4 v = pre[q];
                        float4 h4, l4;
                        h4.x = tf32_rna(v.x); l4.x = tf32_rna(v.x - h4.x);
                        h4.y = tf32_rna(v.y); l4.y = tf32_rna(v.y - h4.y);
                        h4.z = tf32_rna(v.z); l4.z = tf32_rna(v.z - h4.z);
                        h4.w = tf32_rna(v.w); l4.w = tf32_rna(v.w - h4.w);
                        *(float4*)&dh[hso + q * 4] = h4;
                        *(float4*)&dl[hso + q * 4] = l4;
                    }
                }
                __syncthreads();
            }

#pragma unroll
            for (int mt = 0; mt < 2; mt++) {
                int r0 = wm * 32 + mt * 16 + g;
#pragma unroll
                for (int nt = 0; nt < 4; nt++) {
                    int col = wn * 32 + nt * 8 + 2 * tig;
                    *(float2*)&gsm[r0 * 132 + col] =
                        make_float2(acc[mt][nt][0], acc[mt][nt][1]);
                    *(float2*)&gsm[(r0 + 8) * 132 + col] =
                        make_float2(acc[mt][nt][2], acc[mt][nt][3]);
                }
            }
            __syncthreads();
        }

        float* hOut = g_hbuf[(s + 1) & 1] + (size_t)dir * BN * 128;
        size_t xbase = (size_t)t * BN * 512;
#pragma unroll
        for (int i = 0; i < 8; i++) {
            int pj = tid + i * 512;
            int pp = pj >> 5, jj = pj & 31;
            int p = p0 + pp;
            int j = j0 + jj;
            const float* xr = xp + xbase + (size_t)p * 512 + j;
            float gi = xr[0], gf = xr[128], gg2 = xr[256], go = xr[384];
            if (s > 0) {
                gi  += gsm[pp * 132 + jj];
                gf  += gsm[pp * 132 + 32 + jj];
                gg2 += gsm[pp * 132 + 64 + jj];
                go  += gsm[pp * 132 + 96 + jj];
            }
            size_t hidx = (size_t)p * 128 + j;
            float cold = (s == 0) ? 0.0f : cD[hidx];
            float cn = sigf(gf) * cold + sigf(gi) * tanhfast(gg2);
            float hn = sigf(go) * tanhfast(cn);
            if (s == TSEQ - 1) {
                float hs = hsD[hidx] + hn;
                g_sentpres[(size_t)p * 256 + dir * 128 + j] =
                    tanhfast(hs * (1.0f / 50.0f));
            } else {
                cD[hidx] = cn;
                hOut[hidx] = hn;
                hsD[hidx] = (s == 0) ? hn : (hsD[hidx] + hn);
            }
        }

        if (s < TSEQ - 1) {
            __syncthreads();
            if (tid == 0) {
                __threadfence();
                atomicAdd(&g_sbar[barIdx], 1);
                int target = 4 * (s + 1);
                while (*(volatile int*)&g_sbar[barIdx] < target) { }
                __threadfence();
            }
            __syncthreads();
        }
    }

    __syncthreads();
    if (tid == 0) {
        int old = atomicAdd(&g_sdone[barIdx], 1);
        if (old == 3) {
            g_sbar[barIdx] = 0;
            __threadfence();
            g_sdone[barIdx] = 0;
        }
    }
}

// ============================================================
// Dual-half GEMM with f32x2 (modes 1-4).
// MODE 1 writes gate-interleaved txp: [n][b][j*4+gate] (tag win).
// ============================================================
template <int MODE>
__global__ void __launch_bounds__(256) gemm_dual(
    const float* __restrict__ Aparam, int M, int K, int NB,
    const float* __restrict__ B0, const float* __restrict__ B1,
    const float* __restrict__ bias0, const float* __restrict__ bias1,
    float* __restrict__ outParam)
{
    __shared__ __align__(16) u64 As2[8][128];
    __shared__ __align__(16) float Bs[8][128];

    const float* A;
    if (MODE == 1 || MODE == 2) A = g_sentpres;
    else if (MODE == 3) A = g_tag_out;
    else A = g_agg;
    (void)Aparam;

    int hsel = (blockIdx.y * 128) / NB;
    int g0 = blockIdx.y * 128 - hsel * NB;
    int m0 = blockIdx.x * 128;

    const float* B = hsel ? B1 : B0;
    const float* bias = hsel ? bias1 : bias0;

    float* out;
    if (MODE == 1) out = hsel ? g_txp1 : g_txp0;
    else if (MODE == 2 || MODE == 3) out = hsel ? g_k : g_q;
    else out = outParam;

    int tid = threadIdx.x;
    int tx = tid & 15;
    int ty = tid >> 4;
    int lr = tid >> 1;
    int lc4 = tid & 1;

    u64 acc2[8][4];
#pragma unroll
    for (int i = 0; i < 8; i++)
#pragma unroll
        for (int j = 0; j < 4; j++) acc2[i][j] = 0ULL;

    int KT = K / 8;
    const float* aPtr = A + (size_t)(m0 + lr) * K + lc4 * 4;
    const float* bPtr = B + (size_t)(g0 + lr) * K + lc4 * 4;
    float4 av = *(const float4*)(aPtr);
    float4 bv = *(const float4*)(bPtr);

    for (int kt = 0; kt < KT; kt++) {
        As2[lc4 * 4 + 0][lr] = pk2(av.x, av.x);
        As2[lc4 * 4 + 1][lr] = pk2(av.y, av.y);
        As2[lc4 * 4 + 2][lr] = pk2(av.z, av.z);
        As2[lc4 * 4 + 3][lr] = pk2(av.w, av.w);
        Bs[lc4 * 4 + 0][lr] = bv.x; Bs[lc4 * 4 + 1][lr] = bv.y;
        Bs[lc4 * 4 + 2][lr] = bv.z; Bs[lc4 * 4 + 3][lr] = bv.w;
        __syncthreads();
        if (kt + 1 < KT) {
            av = *(const float4*)(aPtr + (kt + 1) * 8);
            bv = *(const float4*)(bPtr + (kt + 1) * 8);
        }
#pragma unroll
        for (int kk = 0; kk < 8; kk++) {
            u64 b2[4];
#pragma unroll
            for (int jq = 0; jq < 4; jq++)
                b2[jq] = *(const u64*)&Bs[kk][2 * (tx + 16 * jq)];
            u64 a2[8];
#pragma unroll
            for (int i = 0; i < 8; i++) a2[i] = As2[kk][ty * 8 + i];
#pragma unroll
            for (int i = 0; i < 8; i++)
#pragma unroll
                for (int jq = 0; jq < 4; jq++)
                    fma2(acc2[i][jq], a2[i], b2[jq]);
        }
        __syncthreads();
    }

#pragma unroll
    for (int i = 0; i < 8; i++) {
        int m = m0 + ty * 8 + i;
        size_t rowbase;
        if (MODE == 1) {
            int b = m >> 6; int n = m & 63;
            rowbase = ((size_t)n * BB + b) * 512;
        } else {
            rowbase = (size_t)m * 256;
        }
#pragma unroll
        for (int jq = 0; jq < 4; jq++) {
            int gcol = g0 + 2 * (tx + 16 * jq);
            float lo, hi;
            up2(acc2[i][jq], lo, hi);
            float2 bb = *(const float2*)(bias + gcol);
            float o0 = lo + bb.x;
            float o1 = hi + bb.y;
            if (MODE == 1) {
                int gate = gcol >> 7;
                int jl = gcol & 127;
                out[rowbase + jl * 4 + gate] = o0;
                out[rowbase + (jl + 1) * 4 + gate] = o1;
            } else {
                if (MODE == 4) { o0 = fmaxf(o0, 0.f); o1 = fmaxf(o1, 0.f); }
                *(float2*)(out + rowbase + gcol) = make_float2(o0, o1);
            }
        }
    }
}

// ============================================================
// Persistent tag BiLSTM v3: TENSOR CORES (3xTF32),
// xp prefetched at step start (LDG.128, gate-interleaved txp).
// ============================================================
#define TG2_WST  132
#define TG2_HST  132
#define TG2_WSZ  (64 * TG2_WST)
#define TG2_HSZ  (32 * TG2_HST)
#define TG2_SMEM ((2 * TG2_WSZ + 2 * TG2_HSZ + 32 * 68) * 4)

__global__ void __launch_bounds__(256) tag_persistent_tc(
    const float* __restrict__ W0, const float* __restrict__ W1)
{
    extern __shared__ __align__(16) float tg2[];
    float* sWh = tg2;
    float* sWl = tg2 + TG2_WSZ;
    float* sHh = tg2 + 2 * TG2_WSZ;
    float* sHl = sHh + TG2_HSZ;
    float* gsm = sHl + TG2_HSZ;

    int dir = blockIdx.x >> 3;
    int jc = blockIdx.x & 7;
    int j0 = jc * 16;
    const float* W = dir ? W1 : W0;
    const float* xp = dir ? g_txp1 : g_txp0;

    int tid = threadIdx.x;
    int lane = tid & 31, warp = tid >> 5;
    int g = lane >> 2, tig = lane & 3;

    {
        int row = tid >> 2;
        int gg = row >> 4, jr = row & 15;
        int kq = (tid & 3) * 32;
        const float* wrow = W + (size_t)(gg * 128 + j0 + jr) * 128 + kq;
        int so = row * TG2_WST + kq;
#pragma unroll
        for (int q = 0; q < 8; q++) {
            float4 v = *(const float4*)(wrow + q * 4);
            float4 h4, l4;
            h4.x = tf32_rna(v.x); l4.x = tf32_rna(v.x - h4.x);
            h4.y = tf32_rna(v.y); l4.y = tf32_rna(v.y - h4.y);
            h4.z = tf32_rna(v.z); l4.z = tf32_rna(v.z - h4.z);
            h4.w = tf32_rna(v.w); l4.w = tf32_rna(v.w - h4.w);
            *(float4*)&sWh[so + q * 4] = h4;
            *(float4*)&sWl[so + q * 4] = l4;
        }
    }
    __syncthreads();

    float creg[2] = {0.f, 0.f};
    int* bar = &g_tbar2[dir * 32];

    for (int s = 0; s < NSEQ; s++) {
        int t = dir ? (NSEQ - 1 - s) : s;

        // prefetch xp for this step's epilogue
        float4 xv[2];
#pragma unroll
        for (int u = 0; u < 2; u++) {
            int idx = tid + u * 256;
            int b = idx >> 4, jj = idx & 15;
            xv[u] = *(const float4*)(xp + ((size_t)t * BB + b) * 512
                                     + (j0 + jj) * 4);
        }

        if (s > 0) {
            const float* hIn = g_thbuf[s & 1] + (size_t)dir * BB * 128;
            {
                int row = tid >> 3;
                int kq = (tid & 7) * 16;
                const float* hrow = hIn + (size_t)row * 128 + kq;
                int so = row * TG2_HST + kq;
#pragma unroll
                for (int q = 0; q < 4; q++) {
                    float4 v = *(const float4*)(hrow + q * 4);
                    float4 h4, l4;
                    h4.x = tf32_rna(v.x); l4.x = tf32_rna(v.x - h4.x);
                    h4.y = tf32_rna(v.y); l4.y = tf32_rna(v.y - h4.y);
                    h4.z = tf32_rna(v.z); l4.z = tf32_rna(v.z - h4.z);
                    h4.w = tf32_rna(v.w); l4.w = tf32_rna(v.w - h4.w);
                    *(float4*)&sHh[so + q * 4] = h4;
                    *(float4*)&sHl[so + q * 4] = l4;
                }
            }
            __syncthreads();

            float acc[2][4];
#pragma unroll
            for (int mt = 0; mt < 2; mt++)
#pragma unroll
                for (int c = 0; c < 4; c++) acc[mt][c] = 0.0f;

#pragma unroll
            for (int kt = 0; kt < 16; kt++) {
                int kb = kt * 8;
                int br = (warp * 8 + g) * TG2_WST + kb;
                u32 bh[2], bl[2];
                bh[0] = __float_as_uint(sWh[br + tig]);
                bh[1] = __float_as_uint(sWh[br + tig + 4]);
                bl[0] = __float_as_uint(sWl[br + tig]);
                bl[1] = __float_as_uint(sWl[br + tig + 4]);
#pragma unroll
                for (int mt = 0; mt < 2; mt++) {
                    int ar0 = (mt * 16 + g) * TG2_HST + kb;
                    int ar1 = ar0 + 8 * TG2_HST;
                    u32 ah[4], al[4];
                    ah[0] = __float_as_uint(sHh[ar0 + tig]);
                    ah[1] = __float_as_uint(sHh[ar1 + tig]);
                    ah[2] = __float_as_uint(sHh[ar0 + tig + 4]);
                    ah[3] = __float_as_uint(sHh[ar1 + tig + 4]);
                    al[0] = __float_as_uint(sHl[ar0 + tig]);
                    al[1] = __float_as_uint(sHl[ar1 + tig]);
                    al[2] = __float_as_uint(sHl[ar0 + tig + 4]);
                    al[3] = __float_as_uint(sHl[ar1 + tig + 4]);
                    mma_tf32(acc[mt], ah, bh);
                    mma_tf32(acc[mt], al, bh);
                    mma_tf32(acc[mt], ah, bl);
                }
            }

#pragma unroll
            for (int mt = 0; mt < 2; mt++) {
                int r0 = mt * 16 + g;
                int col = warp * 8 + 2 * tig;
                *(float2*)&gsm[r0 * 68 + col] = make_float2(acc[mt][0], acc[mt][1]);
                *(float2*)&gsm[(r0 + 8) * 68 + col] = make_float2(acc[mt][2], acc[mt][3]);
            }
            __syncthreads();
        }

        float* hOut = g_thbuf[(s + 1) & 1] + (size_t)dir * BB * 128;
#pragma unroll
        for (int u = 0; u < 2; u++) {
            int idx = tid + u * 256;
            int b = idx >> 4, jj = idx & 15;
            float gi = xv[u].x, gf = xv[u].y, gg2 = xv[u].z, go = xv[u].w;
            if (s > 0) {
                gi  += gsm[b * 68 + jj];
                gf  += gsm[b * 68 + 16 + jj];
                gg2 += gsm[b * 68 + 32 + jj];
                go  += gsm[b * 68 + 48 + jj];
            }
            float cn = sigf(gf) * creg[u] + sigf(gi) * tanhfast(gg2);
            float hn = sigf(go) * tanhfast(cn);
            creg[u] = cn;
            hOut[(size_t)b * 128 + j0 + jj] = hn;
            g_tag_out[((size_t)b * NSEQ + t) * 256 + dir * 128 + j0 + jj] = tanhfast(hn);
        }

        if (s < NSEQ - 1) {
            __syncthreads();
            if (tid == 0) {
                __threadfence();
                atomicAdd(bar, 1);
                int target = 8 * (s + 1);
                while (*(volatile int*)bar < target) { }
                __threadfence();
            }
            __syncthreads();
        }
    }

    __syncthreads();
    if (tid == 0) {
        int old = atomicAdd(&g_tdone2[dir * 32], 1);
        if (old == 7) {
            g_tbar2[dir * 32] = 0;
            __threadfence();
            g_tdone2[dir * 32] = 0;
        }
    }
}

// ---------------- SPP ----------------
__global__ void __launch_bounds__(256) spp_kernel(int which) {
    int b = blockIdx.x;
    int tid = threadIdx.x;
    __shared__ float qs[64][33];
    __shared__ float ks[64][33];
    __shared__ float segs[64][8];

    float acc[16];
#pragma unroll
    for (int i = 0; i < 16; i++) acc[i] = 0.0f;
    int n = tid >> 2;
    int mBase = (tid & 3) * 16;

    for (int d0 = 0; d0 < 256; d0 += 32) {
        __syncthreads();
        for (int idx = tid; idx < 64 * 32; idx += 256) {
            int r = idx >> 5, cc = idx & 31;
            size_t gi = ((size_t)(b * 64 + r)) * 256 + d0 + cc;
            qs[r][cc] = g_q[gi];
            ks[r][cc] = g_k[gi];
        }
        __syncthreads();
#pragma unroll 4
        for (int dd = 0; dd < 32; dd++) {
            float qv = qs[n][dd];
#pragma unroll
            for (int mm = 0; mm < 16; mm++)
                acc[mm] += qv * ks[mBase + mm][dd];
        }
    }
    float s8a = -3.4e38f, s8b = -3.4e38f;
#pragma unroll
    for (int mm = 0; mm < 8; mm++)  s8a = fmaxf(s8a, acc[mm]);
#pragma unroll
    for (int mm = 8; mm < 16; mm++) s8b = fmaxf(s8b, acc[mm]);
    segs[n][(tid & 3) * 2 + 0] = s8a * 0.0625f;
    segs[n][(tid & 3) * 2 + 1] = s8b * 0.0625f;
    __syncthreads();

    if (tid < 64) {
        float e[8];
#pragma unroll
        for (int i = 0; i < 8; i++) e[i] = segs[tid][i];
        float q4[4], h2[2];
#pragma unroll
        for (int i = 0; i < 4; i++) q4[i] = fmaxf(e[2 * i], e[2 * i + 1]);
        h2[0] = fmaxf(q4[0], q4[1]);
        h2[1] = fmaxf(q4[2], q4[3]);
        float a1 = fmaxf(h2[0], h2[1]);
        float* o = (which ? g_roleFt : g_sentFt) + (size_t)(b * 64 + tid) * 15;
        o[0] = a1;
        o[1] = h2[0]; o[2] = h2[1];
#pragma unroll
        for (int i = 0; i < 4; i++) o[3 + i] = q4[i];
#pragma unroll
        for (int i = 0; i < 8; i++) o[7 + i] = e[i];
    }
}

// ---------------- GCN pre ----------------
__global__ void __launch_bounds__(256) gcn_pre() {
    int b = blockIdx.x;
    int tid = threadIdx.x;
    __shared__ float cosm[64][65];
    __shared__ float xs[64][33];
    __shared__ float inv[64];

    if (tid < 64) {
        const float* xr = g_tag_out + (size_t)(b * 64 + tid) * 256;
        float s = 0.0f;
        for (int d = 0; d < 256; d++) { float v = xr[d]; s += v * v; }
        inv[tid] = 1.0f / (sqrtf(s) + 1e-8f);
    }

    float acc[16];
#pragma unroll
    for (int i = 0; i < 16; i++) acc[i] = 0.0f;
    int n = tid >> 2;
    int mBase = (tid & 3) * 16;

    for (int d0 = 0; d0 < 256; d0 += 32) {
        __syncthreads();
        for (int idx = tid; idx < 64 * 32; idx += 256) {
            int r = idx >> 5, cc = idx & 31;
            xs[r][cc] = g_tag_out[((size_t)(b * 64 + r)) * 256 + d0 + cc];
        }
        __syncthreads();
#pragma unroll 4
        for (int dd = 0; dd < 32; dd++) {
            float xv = xs[n][dd];
#pragma unroll
            for (int mm = 0; mm < 16; mm++)
                acc[mm] += xv * xs[mBase + mm][dd];
        }
    }
#pragma unroll
    for (int mm = 0; mm < 16; mm++)
        cosm[n][mBase + mm] = acc[mm] * inv[n] * inv[mBase + mm];

    int ddBase = (tid & 3) * 8;
    for (int d0 = 0; d0 < 256; d0 += 32) {
        __syncthreads();
        for (int idx = tid; idx < 64 * 32; idx += 256) {
            int r = idx >> 5, cc = idx & 31;
            xs[r][cc] = g_tag_out[((size_t)(b * 64 + r)) * 256 + d0 + cc];
        }
        __syncthreads();
        float r8[8];
#pragma unroll
        for (int i = 0; i < 8; i++) r8[i] = 0.0f;
        for (int m = 0; m < 64; m++) {
            float cv = cosm[n][m];
#pragma unroll
            for (int i = 0; i < 8; i++) r8[i] += cv * xs[m][ddBase + i];
        }
#pragma unroll
        for (int i = 0; i < 8; i++) {
            float v = (r8[i] + 2.0f * xs[n][ddBase + i]) * (1.0f / 66.0f);
            g_agg[(size_t)(b * 64 + n) * 256 + d0 + ddBase + i] = v;
        }
    }
}

// ---------------- classifier + log_softmax ----------------
__global__ void __launch_bounds__(256) cls_kernel(
    const float* __restrict__ W, const float* __restrict__ bias,
    float* __restrict__ out)
{
    __shared__ float Wsh[8][288];
    __shared__ float bsh[8];
    __shared__ float ftile[256][33];

    int tid = threadIdx.x;
    for (int i = tid; i < 8 * 286; i += 256) Wsh[i / 286][i % 286] = W[i];
    if (tid < 8) bsh[tid] = bias[tid];
    __syncthreads();

    int p0 = blockIdx.x * 256;
    int p = p0 + tid;
    float z[8];
#pragma unroll
    for (int c = 0; c < 8; c++) z[c] = bsh[c];

    for (int d0 = 0; d0 < 256; d0 += 32) {
        __syncthreads();
        for (int idx = tid; idx < 256 * 32; idx += 256) {
            int r = idx >> 5, cc = idx & 31;
            ftile[r][cc] = g_tag_out[(size_t)(p0 + r) * 256 + d0 + cc];
        }
        __syncthreads();
#pragma unroll 4
        for (int dd = 0; dd < 32; dd++) {
            float f = ftile[tid][dd];
#pragma unroll
            for (int c = 0; c < 8; c++) z[c] += f * Wsh[c][d0 + dd];
        }
    }
#pragma unroll
    for (int d = 0; d < 15; d++) {
        float f = g_sentFt[(size_t)p * 15 + d];
#pragma unroll
        for (int c = 0; c < 8; c++) z[c] += f * Wsh[c][256 + d];
    }
#pragma unroll
    for (int d = 0; d < 15; d++) {
        float f = g_roleFt[(size_t)p * 15 + d];
#pragma unroll
        for (int c = 0; c < 8; c++) z[c] += f * Wsh[c][271 + d];
    }
    float m = z[0];
#pragma unroll
    for (int c = 1; c < 8; c++) m = fmaxf(m, z[c]);
    float se = 0.0f;
#pragma unroll
    for (int c = 0; c < 8; c++) se += expf(z[c] - m);
    float lse = m + logf(se);
#pragma unroll
    for (int c = 0; c < 8; c++) out[(size_t)p * 8 + c] = z[c] - lse;
}

// ============================================================
extern "C" void kernel_launch(void* const* d_in, const int* in_sizes, int n_in,
                              void* d_out, int out_size)
{
    (void)in_sizes; (void)n_in; (void)out_size;
    const float* documents = (const float*)d_in[0];
    const float* sw_ih_f = (const float*)d_in[1];
    const float* sw_hh_f = (const float*)d_in[2];
    const float* sb_f    = (const float*)d_in[3];
    const float* sw_ih_b = (const float*)d_in[4];
    const float* sw_hh_b = (const float*)d_in[5];
    const float* sb_b    = (const float*)d_in[6];
    const float* sf_Wq   = (const float*)d_in[7];
    const float* sf_bq   = (const float*)d_in[8];
    const float* sf_Wk   = (const float*)d_in[9];
    const float* sf_bk   = (const float*)d_in[10];
    const float* rf_Wq   = (const float*)d_in[11];
    const float* rf_bq   = (const float*)d_in[12];
    const float* rf_Wk   = (const float*)d_in[13];
    const float* rf_bk   = (const float*)d_in[14];
    const float* tw_ih_f = (const float*)d_in[15];
    const float* tw_hh_f = (const float*)d_in[16];
    const float* tb_f    = (const float*)d_in[17];
    const float* tw_ih_b = (const float*)d_in[18];
    const float* tw_hh_b = (const float*)d_in[19];
    const float* tb_b    = (const float*)d_in[20];
    const float* sage_W  = (const float*)d_in[21];
    const float* sage_b  = (const float*)d_in[22];
    const float* cls_W   = (const float*)d_in[23];
    const float* cls_b   = (const float*)d_in[24];
    float* out = (float*)d_out;

    cudaFuncSetAttribute(lstm_sent5, cudaFuncAttributeMaxDynamicSharedMemorySize, S5_SMEM);
    cudaFuncSetAttribute(tag_persistent_tc, cudaFuncAttributeMaxDynamicSharedMemorySize, TG2_SMEM);

    // 1) sentence BiLSTM input projection (contiguous xp, R12)
    gemm_inproj_tc<<<dim3(800, 8), 256>>>(documents, sw_ih_f, sw_ih_b, sb_f, sb_b);
    // 2) sentence recurrence: persistent tensor-core kernel, 512 threads (R12)
    lstm_sent5<<<128, 512, S5_SMEM>>>(sw_hh_f, sw_hh_b);
    // 3) tag BiLSTM input projection (gate-interleaved txp)
    gemm_dual<1><<<dim3(16, 8), 256>>>(nullptr, 2048, 256, 512,
                                       tw_ih_f, tw_ih_b, tb_f, tb_b, nullptr);
    // 4) tag recurrence: persistent tensor-core kernel (with xp prefetch)
    tag_persistent_tc<<<16, 256, TG2_SMEM>>>(tw_hh_f, tw_hh_b);
    // 5) SPP on sentpres -> sentFt
    gemm_dual<2><<<dim3(16, 4), 256>>>(nullptr, 2048, 256, 256,
                                       sf_Wq, sf_Wk, sf_bq, sf_bk, nullptr);
    spp_kernel<<<32, 256>>>(0);
    // 6) SPP on tag_out -> roleFt
    gemm_dual<3><<<dim3(16, 4), 256>>>(nullptr, 2048, 256, 256,
                                       rf_Wq, rf_Wk, rf_bq, rf_bk, nullptr);
    spp_kernel<<<32, 256>>>(1);
    // 7) GCN
    gcn_pre<<<32, 256>>>();
    gemm_dual<4><<<dim3(16, 2), 256>>>(nullptr, 2048, 256, 256,
                                       sage_W, sage_W, sage_b, sage_b, out + 16384);
    // 8) classifier + log_softmax
    cls_kernel<<<8, 256>>>(cls_W, cls_b, out);
}